// round 4
// baseline (speedup 1.0000x reference)
#include <cuda_runtime.h>
#include <cuda_bf16.h>

// ---------------------------------------------------------------------------
// MultitaskLoss fused reduction, single kernel, fully-coalesced loads.
// Source-CE is computed cooperatively by 4-lane groups so that the [B,16]
// tensor is read with contiguous (stride-16B) float4 loads instead of the
// 64B-strided per-sample pattern (64 -> 16 L1 wavefronts per warp-iter).
// ---------------------------------------------------------------------------

#define NTHR 256
#define NBLK 4096            // ~3.5-4.5 waves -> fine-grained tail balancing
#define WARPS_PER_BLK (NTHR / 32)

__device__ float g_part[5 * NBLK];     // [accumulator][block]
__device__ unsigned int g_count;       // zero-init; reset by last block

__device__ __forceinline__ float softplusf(float x) {
    return fmaxf(x, 0.0f) + __logf(1.0f + __expf(-fabsf(x)));
}

__device__ __forceinline__ float pick4(float4 v, int j) {
    float r = v.x;
    r = (j == 1) ? v.y : r;
    r = (j == 2) ? v.z : r;
    r = (j == 3) ? v.w : r;
    return r;
}

__global__ void __launch_bounds__(NTHR)
mtl_kernel(const float*  __restrict__ pb,    // [B]    y_pred_binary
           const float4* __restrict__ pt4,   // [B,4]  y_pred_type
           const float4* __restrict__ ps4,   // [B,16] y_pred_source
           const float*  __restrict__ tb,    // [B]    y_true_binary
           const float4* __restrict__ tt4,   // [B,4]  y_true_type
           const int*    __restrict__ lbl,   // [B]    y_true_source
           float* __restrict__ out,
           int B)
{
    const int lane  = threadIdx.x & 31;
    const int wib   = threadIdx.x >> 5;
    const int gwarp = blockIdx.x * WARPS_PER_BLK + wib;
    const int nwarp = gridDim.x * WARPS_PER_BLK;
    const int c     = lane & 3;      // chunk (which float4 of the 16 logits)
    const int g     = lane >> 2;     // 4-lane group id, 0..7

    float s_b = 0.f, s_t = 0.f, s_ce = 0.f, s_ab = 0.f, s_ac = 0.f;

    const int nchunk = B >> 5;       // full 32-sample chunks

    for (int chunk = gwarp; chunk < nchunk; chunk += nwarp) {
        const int s_base = chunk << 5;
        const int sL = s_base + lane;

        // ---- per-lane own-sample work (all coalesced) ----
        float  xb = pb[sL];
        float  yb = tb[sL];
        float4 xt = pt4[sL];
        float4 yt = tt4[sL];

        s_b += softplusf(xb) - yb * xb;
        s_t += (softplusf(xt.x) - yt.x * xt.x)
             + (softplusf(xt.y) - yt.y * xt.y)
             + (softplusf(xt.z) - yt.z * xt.z)
             + (softplusf(xt.w) - yt.w * xt.w);

        bool bc = (xb >= 0.f);
        bool tc = (xt.x >= 0.f) | (xt.y >= 0.f) | (xt.z >= 0.f) | (xt.w >= 0.f);
        s_ab += (bc != tc) ? 1.f : 0.f;

        unsigned bcbits = __ballot_sync(0xffffffffu, bc);

        // ---- source CE: 4-lane-group cooperative over coalesced loads ----
        #pragma unroll
        for (int k = 0; k < 4; k++) {
            // lane holds chunk c of sample s_base + g + 8k
            float4 v = ps4[4 * s_base + 32 * k + lane];

            float m = fmaxf(fmaxf(v.x, v.y), fmaxf(v.z, v.w));
            m = fmaxf(m, __shfl_xor_sync(0xffffffffu, m, 1));
            m = fmaxf(m, __shfl_xor_sync(0xffffffffu, m, 2));

            float e = __expf(v.x - m) + __expf(v.y - m)
                    + __expf(v.z - m) + __expf(v.w - m);

            int   l  = lbl[s_base + g + 8 * k];         // 32B broadcast load
            float xl = (c == (l >> 2)) ? pick4(v, l & 3) : 0.f;

            e  += __shfl_xor_sync(0xffffffffu, e, 1);
            xl += __shfl_xor_sync(0xffffffffu, xl, 1);
            e  += __shfl_xor_sync(0xffffffffu, e, 2);
            xl += __shfl_xor_sync(0xffffffffu, xl, 2);

            if (c == 0) {                // one lane per group finalizes
                s_ce += m + __logf(e) - xl;
                bool sc  = (v.x < m);    // v.x == ps[0] on the c==0 lane
                bool bcs = (bcbits >> (g + 8 * k)) & 1u;
                s_ac += (bcs != sc) ? 1.f : 0.f;
            }
        }
    }

    // ---- tail samples [32*nchunk, B): scalar path, warp 0 only ----
    if (gwarp == 0) {
        for (int i = (nchunk << 5) + lane; i < B; i += 32) {
            float  xb = pb[i];
            float  yb = tb[i];
            float4 xt = pt4[i];
            float4 yt = tt4[i];
            s_b += softplusf(xb) - yb * xb;
            s_t += (softplusf(xt.x) - yt.x * xt.x)
                 + (softplusf(xt.y) - yt.y * xt.y)
                 + (softplusf(xt.z) - yt.z * xt.z)
                 + (softplusf(xt.w) - yt.w * xt.w);
            bool tc = (xt.x >= 0.f) | (xt.y >= 0.f) | (xt.z >= 0.f) | (xt.w >= 0.f);

            float4 a = ps4[4 * i + 0], b = ps4[4 * i + 1];
            float4 cc = ps4[4 * i + 2], d = ps4[4 * i + 3];
            float m = fmaxf(
                fmaxf(fmaxf(fmaxf(a.x, a.y), fmaxf(a.z, a.w)),
                      fmaxf(fmaxf(b.x, b.y), fmaxf(b.z, b.w))),
                fmaxf(fmaxf(fmaxf(cc.x, cc.y), fmaxf(cc.z, cc.w)),
                      fmaxf(fmaxf(d.x, d.y), fmaxf(d.z, d.w))));
            float se = __expf(a.x-m)+__expf(a.y-m)+__expf(a.z-m)+__expf(a.w-m)
                     + __expf(b.x-m)+__expf(b.y-m)+__expf(b.z-m)+__expf(b.w-m)
                     + __expf(cc.x-m)+__expf(cc.y-m)+__expf(cc.z-m)+__expf(cc.w-m)
                     + __expf(d.x-m)+__expf(d.y-m)+__expf(d.z-m)+__expf(d.w-m);
            int l = lbl[i];
            float4 v = (l < 8) ? ((l < 4) ? a : b) : ((l < 12) ? cc : d);
            s_ce += m + __logf(se) - pick4(v, l & 3);

            bool bc = (xb >= 0.f);
            bool sc = (a.x < m);
            s_ab += (bc != tc) ? 1.f : 0.f;
            s_ac += (bc != sc) ? 1.f : 0.f;
        }
    }

    // ---- block reduction ----
    #pragma unroll
    for (int o = 16; o; o >>= 1) {
        s_b  += __shfl_down_sync(0xffffffffu, s_b,  o);
        s_t  += __shfl_down_sync(0xffffffffu, s_t,  o);
        s_ce += __shfl_down_sync(0xffffffffu, s_ce, o);
        s_ab += __shfl_down_sync(0xffffffffu, s_ab, o);
        s_ac += __shfl_down_sync(0xffffffffu, s_ac, o);
    }

    __shared__ float sm[5][WARPS_PER_BLK];
    if (lane == 0) {
        sm[0][wib] = s_b;  sm[1][wib] = s_t;  sm[2][wib] = s_ce;
        sm[3][wib] = s_ab; sm[4][wib] = s_ac;
    }
    __syncthreads();

    if (threadIdx.x == 0) {
        float t0=0.f, t1=0.f, t2=0.f, t3=0.f, t4=0.f;
        #pragma unroll
        for (int k = 0; k < WARPS_PER_BLK; k++) {
            t0 += sm[0][k]; t1 += sm[1][k]; t2 += sm[2][k];
            t3 += sm[3][k]; t4 += sm[4][k];
        }
        g_part[0 * NBLK + blockIdx.x] = t0;
        g_part[1 * NBLK + blockIdx.x] = t1;
        g_part[2 * NBLK + blockIdx.x] = t2;
        g_part[3 * NBLK + blockIdx.x] = t3;
        g_part[4 * NBLK + blockIdx.x] = t4;
    }

    // ---- last-block finalize ----
    __shared__ bool is_last;
    if (threadIdx.x == 0) {
        __threadfence();
        unsigned int done = atomicAdd(&g_count, 1u);
        is_last = (done == (unsigned int)(gridDim.x - 1));
    }
    __syncthreads();
    if (!is_last) return;

    __threadfence();

    double acc[5] = {0.0, 0.0, 0.0, 0.0, 0.0};
    for (int bidx = threadIdx.x; bidx < NBLK; bidx += NTHR) {
        #pragma unroll
        for (int k = 0; k < 5; k++)
            acc[k] += (double)g_part[k * NBLK + bidx];
    }

    #pragma unroll
    for (int o = 16; o; o >>= 1) {
        #pragma unroll
        for (int k = 0; k < 5; k++)
            acc[k] += __shfl_down_sync(0xffffffffu, acc[k], o);
    }

    __shared__ double smd[5][WARPS_PER_BLK];
    if (lane == 0) {
        #pragma unroll
        for (int k = 0; k < 5; k++) smd[k][wib] = acc[k];
    }
    __syncthreads();

    if (threadIdx.x == 0) {
        double t[5] = {0.0, 0.0, 0.0, 0.0, 0.0};
        #pragma unroll
        for (int w = 0; w < WARPS_PER_BLK; w++) {
            #pragma unroll
            for (int k = 0; k < 5; k++) t[k] += smd[k][w];
        }
        double Bd = (double)B;
        double loss = t[0] / Bd            // binary BCE mean
                    + t[1] / (Bd * 4.0)    // type BCE mean over B*T
                    + t[2] / Bd            // CE mean
                    + t[3] / Bd            // cons_ab mean
                    + t[4] / Bd;           // cons_ac mean
        out[0] = (float)loss;
        g_count = 0;                       // reset for next graph replay
    }
}

extern "C" void kernel_launch(void* const* d_in, const int* in_sizes, int n_in,
                              void* d_out, int out_size)
{
    const float*  pb  = (const float*) d_in[0];   // y_pred_binary  [B]
    const float4* pt4 = (const float4*)d_in[1];   // y_pred_type    [B,4]
    const float4* ps4 = (const float4*)d_in[2];   // y_pred_source  [B,16]
    const float*  tb  = (const float*) d_in[3];   // y_true_binary  [B]
    const float4* tt4 = (const float4*)d_in[4];   // y_true_type    [B,4]
    const int*    lbl = (const int*)   d_in[5];   // y_true_source  [B]
    float* out = (float*)d_out;

    int B = in_sizes[0];

    mtl_kernel<<<NBLK, NTHR>>>(pb, pt4, ps4, tb, tt4, lbl, out, B);
}

// round 5
// speedup vs baseline: 1.1995x; 1.1995x over previous
#include <cuda_runtime.h>
#include <cuda_bf16.h>

// ---------------------------------------------------------------------------
// MultitaskLoss fused reduction, single kernel.
// R1 compute body (plain cached per-sample float4 loads — measured 5.9 TB/s)
// + R2 last-block-done finalize (saves the 12us second launch).
// No __ldcs (it broke L1 line reuse of the strided ps4 loads: R2 regression).
// No cooperative shuffles (issue-bound: R4 regression).
// ---------------------------------------------------------------------------

#define NBLK 1184          // 148 SMs * 8 blocks * 256 thr = one full wave
#define NTHR 256
#define WARPS_PER_BLK (NTHR / 32)

__device__ float g_part[5 * NBLK];     // [accumulator][block]
__device__ unsigned int g_count;       // zero-init; reset by last block

// Stable softplus: sp(x) = max(x,0) + log(1 + exp(-|x|)).
__device__ __forceinline__ float softplusf(float x) {
    return fmaxf(x, 0.0f) + __logf(1.0f + __expf(-fabsf(x)));
}

__device__ __forceinline__ float pick4(float4 v, int j) {
    float r = v.x;
    r = (j == 1) ? v.y : r;
    r = (j == 2) ? v.z : r;
    r = (j == 3) ? v.w : r;
    return r;
}

__global__ void __launch_bounds__(NTHR)
mtl_fused_kernel(const float*  __restrict__ pb,    // [B]    y_pred_binary
                 const float4* __restrict__ pt4,   // [B,4]  y_pred_type
                 const float4* __restrict__ ps4,   // [B,16] y_pred_source
                 const float*  __restrict__ tb,    // [B]    y_true_binary
                 const float4* __restrict__ tt4,   // [B,4]  y_true_type
                 const int*    __restrict__ lbl,   // [B]    y_true_source
                 float* __restrict__ out,
                 int B)
{
    float s_b = 0.f, s_t = 0.f, s_ce = 0.f, s_ab = 0.f, s_ac = 0.f;

    const int stride = gridDim.x * blockDim.x;
    for (int i = blockIdx.x * blockDim.x + threadIdx.x; i < B; i += stride) {
        // ---- issue all loads up front (MLP batching; plain cached) ----
        float  xb = pb[i];
        float  yb = tb[i];
        float4 xt = pt4[i];
        float4 yt = tt4[i];
        float4 a  = ps4[4 * i + 0];
        float4 b  = ps4[4 * i + 1];
        float4 c  = ps4[4 * i + 2];
        float4 d  = ps4[4 * i + 3];
        int    l  = lbl[i];

        // ---- binary BCE: sp(x) - y*x ----
        s_b += softplusf(xb) - yb * xb;

        // ---- type BCE over 4 logits ----
        s_t += (softplusf(xt.x) - yt.x * xt.x)
             + (softplusf(xt.y) - yt.y * xt.y)
             + (softplusf(xt.z) - yt.z * xt.z)
             + (softplusf(xt.w) - yt.w * xt.w);
        bool type_c = (xt.x >= 0.f) | (xt.y >= 0.f) | (xt.z >= 0.f) | (xt.w >= 0.f);

        // ---- source CE over 16 logits ----
        float m = fmaxf(
            fmaxf(fmaxf(fmaxf(a.x, a.y), fmaxf(a.z, a.w)),
                  fmaxf(fmaxf(b.x, b.y), fmaxf(b.z, b.w))),
            fmaxf(fmaxf(fmaxf(c.x, c.y), fmaxf(c.z, c.w)),
                  fmaxf(fmaxf(d.x, d.y), fmaxf(d.z, d.w))));

        float se = __expf(a.x - m) + __expf(a.y - m) + __expf(a.z - m) + __expf(a.w - m)
                 + __expf(b.x - m) + __expf(b.y - m) + __expf(b.z - m) + __expf(b.w - m)
                 + __expf(c.x - m) + __expf(c.y - m) + __expf(c.z - m) + __expf(c.w - m)
                 + __expf(d.x - m) + __expf(d.y - m) + __expf(d.z - m) + __expf(d.w - m);

        float4 v = (l < 8) ? ((l < 4) ? a : b) : ((l < 12) ? c : d);
        float xl = pick4(v, l & 3);
        s_ce += m + __logf(se) - xl;

        // ---- consistency bits ----
        bool bc = (xb >= 0.f);            // sigmoid(x) >= 0.5  <=>  x >= 0
        bool sc = (a.x < m);              // argmax > 0 (first-occurrence rule)
        s_ab += (bc != type_c) ? 1.f : 0.f;
        s_ac += (bc != sc)     ? 1.f : 0.f;
    }

    // ---- block reduction: warp shuffle, then smem across warps ----
    #pragma unroll
    for (int o = 16; o; o >>= 1) {
        s_b  += __shfl_down_sync(0xffffffffu, s_b,  o);
        s_t  += __shfl_down_sync(0xffffffffu, s_t,  o);
        s_ce += __shfl_down_sync(0xffffffffu, s_ce, o);
        s_ab += __shfl_down_sync(0xffffffffu, s_ab, o);
        s_ac += __shfl_down_sync(0xffffffffu, s_ac, o);
    }

    __shared__ float sm[5][WARPS_PER_BLK];
    int warp = threadIdx.x >> 5;
    int lane = threadIdx.x & 31;
    if (lane == 0) {
        sm[0][warp] = s_b;
        sm[1][warp] = s_t;
        sm[2][warp] = s_ce;
        sm[3][warp] = s_ab;
        sm[4][warp] = s_ac;
    }
    __syncthreads();

    if (threadIdx.x == 0) {
        float t0 = 0.f, t1 = 0.f, t2 = 0.f, t3 = 0.f, t4 = 0.f;
        #pragma unroll
        for (int k = 0; k < WARPS_PER_BLK; k++) {
            t0 += sm[0][k]; t1 += sm[1][k]; t2 += sm[2][k];
            t3 += sm[3][k]; t4 += sm[4][k];
        }
        g_part[0 * NBLK + blockIdx.x] = t0;
        g_part[1 * NBLK + blockIdx.x] = t1;
        g_part[2 * NBLK + blockIdx.x] = t2;
        g_part[3 * NBLK + blockIdx.x] = t3;
        g_part[4 * NBLK + blockIdx.x] = t4;
    }

    // ---- last-block-done finalize (threadfence reduction) ----
    __shared__ bool is_last;
    if (threadIdx.x == 0) {
        __threadfence();
        unsigned int done = atomicAdd(&g_count, 1u);
        is_last = (done == (unsigned int)(gridDim.x - 1));
    }
    __syncthreads();
    if (!is_last) return;

    __threadfence();  // make other blocks' partial writes visible

    double acc[5] = {0.0, 0.0, 0.0, 0.0, 0.0};
    for (int bidx = threadIdx.x; bidx < NBLK; bidx += NTHR) {
        #pragma unroll
        for (int k = 0; k < 5; k++)
            acc[k] += (double)g_part[k * NBLK + bidx];
    }

    #pragma unroll
    for (int o = 16; o; o >>= 1) {
        #pragma unroll
        for (int k = 0; k < 5; k++)
            acc[k] += __shfl_down_sync(0xffffffffu, acc[k], o);
    }

    __shared__ double smd[5][WARPS_PER_BLK];
    if (lane == 0) {
        #pragma unroll
        for (int k = 0; k < 5; k++) smd[k][warp] = acc[k];
    }
    __syncthreads();

    if (threadIdx.x == 0) {
        double t[5] = {0.0, 0.0, 0.0, 0.0, 0.0};
        #pragma unroll
        for (int w = 0; w < WARPS_PER_BLK; w++) {
            #pragma unroll
            for (int k = 0; k < 5; k++) t[k] += smd[k][w];
        }
        double Bd = (double)B;
        double loss = t[0] / Bd            // binary BCE mean
                    + t[1] / (Bd * 4.0)    // type BCE mean over B*T
                    + t[2] / Bd            // CE mean
                    + t[3] / Bd            // cons_ab mean
                    + t[4] / Bd;           // cons_ac mean
        out[0] = (float)loss;
        g_count = 0;                       // reset for next graph replay
    }
}

extern "C" void kernel_launch(void* const* d_in, const int* in_sizes, int n_in,
                              void* d_out, int out_size)
{
    const float*  pb  = (const float*) d_in[0];   // y_pred_binary  [B]
    const float4* pt4 = (const float4*)d_in[1];   // y_pred_type    [B,4]
    const float4* ps4 = (const float4*)d_in[2];   // y_pred_source  [B,16]
    const float*  tb  = (const float*) d_in[3];   // y_true_binary  [B]
    const float4* tt4 = (const float4*)d_in[4];   // y_true_type    [B,4]
    const int*    lbl = (const int*)   d_in[5];   // y_true_source  [B]
    float* out = (float*)d_out;

    int B = in_sizes[0];

    mtl_fused_kernel<<<NBLK, NTHR>>>(pb, pt4, ps4, tb, tt4, lbl, out, B);
}